// round 1
// baseline (speedup 1.0000x reference)
#include <cuda_runtime.h>

#define FULL 0xffffffffu

constexpr int N = 65536;
constexpr int D = 512;
constexpr int RPW = 16;                         // rows per warp in the streaming kernels
constexpr int STREAM_THREADS = 256;             // 8 warps
constexpr int STREAM_BLOCKS = N / RPW / (STREAM_THREADS / 32);  // 512

// Scratch (allocation-free: __device__ globals)
__device__ __align__(16) float g_s[D];
__device__ __align__(16) float g_t[D];
__device__ float    g_c;
__device__ unsigned g_maxkey;
__device__ float    g_sumexp;
__device__ float    g_x[N];

__device__ __forceinline__ float warp_sum(float v) {
#pragma unroll
    for (int o = 16; o; o >>= 1) v += __shfl_xor_sync(FULL, v, o);
    return v;
}

// ---------------------------------------------------------------------------
// K0: zero the accumulators (runs every call; graph is replayed)
// ---------------------------------------------------------------------------
__global__ void k_init() {
    int t = threadIdx.x;
    g_s[t] = 0.0f;
    g_t[t] = 0.0f;
    if (t == 0) { g_c = 0.0f; g_maxkey = 0u; g_sumexp = 0.0f; }
}

// ---------------------------------------------------------------------------
// K1: pass 1 over inputs. Per row n: k = inputs[n]·key_w + key_b,
//     then s += inputs[n] * k  (row held in registers, read once).
// Warp layout: lane l owns float4 slots {l, l+32, l+64, l+96} of the 128
// float4s in a row  → d-indices {4l..4l+3, 128+4l.., 256+.., 384+..}.
// ---------------------------------------------------------------------------
__global__ void __launch_bounds__(STREAM_THREADS)
k1(const float* __restrict__ inp, const float* __restrict__ kw,
   const float* __restrict__ kb) {
    __shared__ float sblk[D];
    const int tid = threadIdx.x;
    for (int i = tid; i < D; i += STREAM_THREADS) sblk[i] = 0.0f;
    __syncthreads();

    const int lane = tid & 31;
    const int warp = (blockIdx.x * STREAM_THREADS + tid) >> 5;
    const float4* kwp = (const float4*)kw;
    const float4 w0 = kwp[lane], w1 = kwp[lane + 32],
                 w2 = kwp[lane + 64], w3 = kwp[lane + 96];
    const float kb0 = kb[0];

    float4 s0 = {0,0,0,0}, s1 = {0,0,0,0}, s2 = {0,0,0,0}, s3 = {0,0,0,0};
    const int row0 = warp * RPW;

#pragma unroll 2
    for (int r = 0; r < RPW; r++) {
        const float4* rp = (const float4*)(inp + (size_t)(row0 + r) * D);
        const float4 a0 = rp[lane], a1 = rp[lane + 32],
                     a2 = rp[lane + 64], a3 = rp[lane + 96];
        // 4 independent FMA chains, then combine
        float d0 = a0.x * w0.x; d0 = fmaf(a0.y, w0.y, d0);
        d0 = fmaf(a0.z, w0.z, d0); d0 = fmaf(a0.w, w0.w, d0);
        float d1 = a1.x * w1.x; d1 = fmaf(a1.y, w1.y, d1);
        d1 = fmaf(a1.z, w1.z, d1); d1 = fmaf(a1.w, w1.w, d1);
        float d2 = a2.x * w2.x; d2 = fmaf(a2.y, w2.y, d2);
        d2 = fmaf(a2.z, w2.z, d2); d2 = fmaf(a2.w, w2.w, d2);
        float d3 = a3.x * w3.x; d3 = fmaf(a3.y, w3.y, d3);
        d3 = fmaf(a3.z, w3.z, d3); d3 = fmaf(a3.w, w3.w, d3);
        const float kv = warp_sum((d0 + d1) + (d2 + d3)) + kb0;

        s0.x = fmaf(a0.x, kv, s0.x); s0.y = fmaf(a0.y, kv, s0.y);
        s0.z = fmaf(a0.z, kv, s0.z); s0.w = fmaf(a0.w, kv, s0.w);
        s1.x = fmaf(a1.x, kv, s1.x); s1.y = fmaf(a1.y, kv, s1.y);
        s1.z = fmaf(a1.z, kv, s1.z); s1.w = fmaf(a1.w, kv, s1.w);
        s2.x = fmaf(a2.x, kv, s2.x); s2.y = fmaf(a2.y, kv, s2.y);
        s2.z = fmaf(a2.z, kv, s2.z); s2.w = fmaf(a2.w, kv, s2.w);
        s3.x = fmaf(a3.x, kv, s3.x); s3.y = fmaf(a3.y, kv, s3.y);
        s3.z = fmaf(a3.z, kv, s3.z); s3.w = fmaf(a3.w, kv, s3.w);
    }

    // block-level pre-reduction in shared, then 512 global atomics per block
    const int b0 = 4 * lane;
    atomicAdd(&sblk[b0 + 0],       s0.x); atomicAdd(&sblk[b0 + 1],       s0.y);
    atomicAdd(&sblk[b0 + 2],       s0.z); atomicAdd(&sblk[b0 + 3],       s0.w);
    atomicAdd(&sblk[128 + b0 + 0], s1.x); atomicAdd(&sblk[128 + b0 + 1], s1.y);
    atomicAdd(&sblk[128 + b0 + 2], s1.z); atomicAdd(&sblk[128 + b0 + 3], s1.w);
    atomicAdd(&sblk[256 + b0 + 0], s2.x); atomicAdd(&sblk[256 + b0 + 1], s2.y);
    atomicAdd(&sblk[256 + b0 + 2], s2.z); atomicAdd(&sblk[256 + b0 + 3], s2.w);
    atomicAdd(&sblk[384 + b0 + 0], s3.x); atomicAdd(&sblk[384 + b0 + 1], s3.y);
    atomicAdd(&sblk[384 + b0 + 2], s3.z); atomicAdd(&sblk[384 + b0 + 3], s3.w);
    __syncthreads();
    for (int i = tid; i < D; i += STREAM_THREADS) atomicAdd(&g_s[i], sblk[i]);
}

// ---------------------------------------------------------------------------
// K2: t[d] = sum_j value_w[j][d] * s[j]   (j split over 8 blocks)
//     c    = value_b · s                  (block 0)
// ---------------------------------------------------------------------------
__global__ void k2(const float* __restrict__ vw, const float* __restrict__ vb) {
    __shared__ float ssh[D];
    const int tid = threadIdx.x;            // 512 threads
    ssh[tid] = g_s[tid];
    __syncthreads();

    const int j0 = blockIdx.x * 64;
    float acc = 0.0f;
#pragma unroll 8
    for (int j = 0; j < 64; j++)
        acc = fmaf(vw[(size_t)(j0 + j) * D + tid], ssh[j0 + j], acc);
    atomicAdd(&g_t[tid], acc);

    if (blockIdx.x == 0) {
        __shared__ float red[D];
        red[tid] = vb[tid] * ssh[tid];
        __syncthreads();
        for (int sft = 256; sft > 0; sft >>= 1) {
            if (tid < sft) red[tid] += red[tid + sft];
            __syncthreads();
        }
        if (tid == 0) g_c = red[0];
    }
}

// ---------------------------------------------------------------------------
// K3: pass 2 over inputs: x[n] = inputs[n]·t + c, track global max
// ---------------------------------------------------------------------------
__global__ void __launch_bounds__(STREAM_THREADS)
k3(const float* __restrict__ inp) {
    const int tid = threadIdx.x;
    const int lane = tid & 31;
    const int warp = (blockIdx.x * STREAM_THREADS + tid) >> 5;
    const float4* tp = (const float4*)g_t;
    const float4 w0 = tp[lane], w1 = tp[lane + 32],
                 w2 = tp[lane + 64], w3 = tp[lane + 96];
    const float c = g_c;
    float maxv = -3.4e38f;
    const int row0 = warp * RPW;

#pragma unroll 2
    for (int r = 0; r < RPW; r++) {
        const float4* rp = (const float4*)(inp + (size_t)(row0 + r) * D);
        const float4 a0 = rp[lane], a1 = rp[lane + 32],
                     a2 = rp[lane + 64], a3 = rp[lane + 96];
        float d0 = a0.x * w0.x; d0 = fmaf(a0.y, w0.y, d0);
        d0 = fmaf(a0.z, w0.z, d0); d0 = fmaf(a0.w, w0.w, d0);
        float d1 = a1.x * w1.x; d1 = fmaf(a1.y, w1.y, d1);
        d1 = fmaf(a1.z, w1.z, d1); d1 = fmaf(a1.w, w1.w, d1);
        float d2 = a2.x * w2.x; d2 = fmaf(a2.y, w2.y, d2);
        d2 = fmaf(a2.z, w2.z, d2); d2 = fmaf(a2.w, w2.w, d2);
        float d3 = a3.x * w3.x; d3 = fmaf(a3.y, w3.y, d3);
        d3 = fmaf(a3.z, w3.z, d3); d3 = fmaf(a3.w, w3.w, d3);
        const float x = warp_sum((d0 + d1) + (d2 + d3)) + c;
        if (lane == 0) g_x[row0 + r] = x;
        maxv = fmaxf(maxv, x);
    }

    if (lane == 0) {
        unsigned u = __float_as_uint(maxv);
        unsigned key = (u & 0x80000000u) ? ~u : (u | 0x80000000u);
        atomicMax(&g_maxkey, key);
    }
}

// ---------------------------------------------------------------------------
// K4: e[n] = exp(x[n] - max) (written back into g_x), sumexp += block partial
// ---------------------------------------------------------------------------
__global__ void k4() {
    const unsigned key = g_maxkey;
    const unsigned ub = (key & 0x80000000u) ? (key & 0x7fffffffu) : ~key;
    const float gmax = __uint_as_float(ub);

    const int i = blockIdx.x * blockDim.x + threadIdx.x;
    const float e = expf(g_x[i] - gmax);
    g_x[i] = e;

    float ws = warp_sum(e);
    __shared__ float sh[8];
    const int lane = threadIdx.x & 31, w = threadIdx.x >> 5;
    if (lane == 0) sh[w] = ws;
    __syncthreads();
    if (w == 0) {
        float v = (lane < 8) ? sh[lane] : 0.0f;
        v = warp_sum(v);
        if (lane == 0) atomicAdd(&g_sumexp, v);
    }
}

// ---------------------------------------------------------------------------
// K5: out[n] = e[n] / sumexp
// ---------------------------------------------------------------------------
__global__ void k5(float* __restrict__ out) {
    const int i = blockIdx.x * blockDim.x + threadIdx.x;
    out[i] = g_x[i] * (1.0f / g_sumexp);
}

// ---------------------------------------------------------------------------
extern "C" void kernel_launch(void* const* d_in, const int* in_sizes, int n_in,
                              void* d_out, int out_size) {
    (void)in_sizes; (void)n_in; (void)out_size;
    const float* inp = (const float*)d_in[0];   // [N, D]
    const float* kw  = (const float*)d_in[1];   // [1, D]
    const float* kb  = (const float*)d_in[2];   // [1]
    const float* vw  = (const float*)d_in[3];   // [D, D]
    const float* vb  = (const float*)d_in[4];   // [D]
    float* out = (float*)d_out;                 // [N, 1]

    k_init<<<1, D>>>();
    k1<<<STREAM_BLOCKS, STREAM_THREADS>>>(inp, kw, kb);
    k2<<<8, D>>>(vw, vb);
    k3<<<STREAM_BLOCKS, STREAM_THREADS>>>(inp);
    k4<<<N / 256, 256>>>();
    k5<<<N / 256, 256>>>(out);
}

// round 3
// speedup vs baseline: 1.2760x; 1.2760x over previous
#include <cuda_runtime.h>

#define FULL 0xffffffffu

constexpr int N = 65536;
constexpr int D = 512;
constexpr int NPAIRS = N / 2;              // 32768 row pairs

constexpr int TPB = 256;                   // 8 warps/block
constexpr int K1_BLOCKS = 444;             // 3 CTAs/SM * 148 SMs (fully resident)
constexpr int K1_WARPS  = K1_BLOCKS * (TPB / 32);   // 3552
constexpr int K3_BLOCKS = 592;             // 4 CTAs/SM * 148 SMs
constexpr int K3_WARPS  = K3_BLOCKS * (TPB / 32);   // 4736

// Scratch (allocation-free: __device__ globals)
__device__ __align__(16) float g_s[D];
__device__ __align__(16) float g_t[D];
__device__ float    g_c;
__device__ unsigned g_maxkey;
__device__ float    g_sumexp;
__device__ __align__(16) float g_x[N];

__device__ __forceinline__ float warp_sum(float v) {
#pragma unroll
    for (int o = 16; o; o >>= 1) v += __shfl_xor_sync(FULL, v, o);
    return v;
}

__device__ __forceinline__ float dot4(float4 a, float4 w) {
    return fmaf(a.w, w.w, fmaf(a.z, w.z, fmaf(a.y, w.y, a.x * w.x)));
}

// ---------------------------------------------------------------------------
// K0: zero the accumulators (graph is replayed; must reset every call)
// ---------------------------------------------------------------------------
__global__ void k_init() {
    int t = threadIdx.x;
    g_s[t] = 0.0f;
    g_t[t] = 0.0f;
    if (t == 0) { g_c = 0.0f; g_maxkey = 0u; g_sumexp = 0.0f; }
}

// ---------------------------------------------------------------------------
// K1: pass 1. Per row n: k = inputs[n]·key_w + key_b; s += inputs[n]*k.
// Persistent grid-stride over row PAIRS; 8 front-batched LDG.128 per iter.
// Lane l owns float4 slots {l, l+32, l+64, l+96} of the 128 float4s per row.
// ---------------------------------------------------------------------------
__global__ void __launch_bounds__(TPB, 3)
k1(const float* __restrict__ inp, const float* __restrict__ kw,
   const float* __restrict__ kb) {
    __shared__ float sblk[D];
    const int tid = threadIdx.x;
    for (int i = tid; i < D; i += TPB) sblk[i] = 0.0f;
    __syncthreads();

    const int lane = tid & 31;
    const int gw = (blockIdx.x * TPB + tid) >> 5;

    const float4* __restrict__ kw4 = (const float4*)kw;
    const float4 w0 = kw4[lane],      w1 = kw4[lane + 32],
                 w2 = kw4[lane + 64], w3 = kw4[lane + 96];
    const float kb0 = kb[0];

    float4 s0 = {0,0,0,0}, s1 = {0,0,0,0}, s2 = {0,0,0,0}, s3 = {0,0,0,0};

    for (int p = gw; p < NPAIRS; p += K1_WARPS) {
        const float4* __restrict__ rA = (const float4*)inp + (size_t)(2 * p) * (D / 4);
        const float4* __restrict__ rB = rA + (D / 4);
        // front-batch all 8 loads (independent -> max MLP)
        const float4 a0 = rA[lane],      a1 = rA[lane + 32],
                     a2 = rA[lane + 64], a3 = rA[lane + 96];
        const float4 b0 = rB[lane],      b1 = rB[lane + 32],
                     b2 = rB[lane + 64], b3 = rB[lane + 96];

        float dA = (dot4(a0, w0) + dot4(a1, w1)) + (dot4(a2, w2) + dot4(a3, w3));
        float dB = (dot4(b0, w0) + dot4(b1, w1)) + (dot4(b2, w2) + dot4(b3, w3));
        // two independent butterfly chains, interleaved
#pragma unroll
        for (int o = 16; o; o >>= 1) {
            dA += __shfl_xor_sync(FULL, dA, o);
            dB += __shfl_xor_sync(FULL, dB, o);
        }
        const float kvA = dA + kb0;
        const float kvB = dB + kb0;

        s0.x = fmaf(a0.x, kvA, fmaf(b0.x, kvB, s0.x));
        s0.y = fmaf(a0.y, kvA, fmaf(b0.y, kvB, s0.y));
        s0.z = fmaf(a0.z, kvA, fmaf(b0.z, kvB, s0.z));
        s0.w = fmaf(a0.w, kvA, fmaf(b0.w, kvB, s0.w));
        s1.x = fmaf(a1.x, kvA, fmaf(b1.x, kvB, s1.x));
        s1.y = fmaf(a1.y, kvA, fmaf(b1.y, kvB, s1.y));
        s1.z = fmaf(a1.z, kvA, fmaf(b1.z, kvB, s1.z));
        s1.w = fmaf(a1.w, kvA, fmaf(b1.w, kvB, s1.w));
        s2.x = fmaf(a2.x, kvA, fmaf(b2.x, kvB, s2.x));
        s2.y = fmaf(a2.y, kvA, fmaf(b2.y, kvB, s2.y));
        s2.z = fmaf(a2.z, kvA, fmaf(b2.z, kvB, s2.z));
        s2.w = fmaf(a2.w, kvA, fmaf(b2.w, kvB, s2.w));
        s3.x = fmaf(a3.x, kvA, fmaf(b3.x, kvB, s3.x));
        s3.y = fmaf(a3.y, kvA, fmaf(b3.y, kvB, s3.y));
        s3.z = fmaf(a3.z, kvA, fmaf(b3.z, kvB, s3.z));
        s3.w = fmaf(a3.w, kvA, fmaf(b3.w, kvB, s3.w));
    }

    // block pre-reduction in shared, then 512 global atomics per block
    const int b0i = 4 * lane;
    atomicAdd(&sblk[b0i + 0],       s0.x); atomicAdd(&sblk[b0i + 1],       s0.y);
    atomicAdd(&sblk[b0i + 2],       s0.z); atomicAdd(&sblk[b0i + 3],       s0.w);
    atomicAdd(&sblk[128 + b0i + 0], s1.x); atomicAdd(&sblk[128 + b0i + 1], s1.y);
    atomicAdd(&sblk[128 + b0i + 2], s1.z); atomicAdd(&sblk[128 + b0i + 3], s1.w);
    atomicAdd(&sblk[256 + b0i + 0], s2.x); atomicAdd(&sblk[256 + b0i + 1], s2.y);
    atomicAdd(&sblk[256 + b0i + 2], s2.z); atomicAdd(&sblk[256 + b0i + 3], s2.w);
    atomicAdd(&sblk[384 + b0i + 0], s3.x); atomicAdd(&sblk[384 + b0i + 1], s3.y);
    atomicAdd(&sblk[384 + b0i + 2], s3.z); atomicAdd(&sblk[384 + b0i + 3], s3.w);
    __syncthreads();
    for (int i = tid; i < D; i += TPB) atomicAdd(&g_s[i], sblk[i]);
}

// ---------------------------------------------------------------------------
// K2: t[d] = sum_j value_w[j][d] * s[j]  (32 blocks, 16 j's each, atomic merge)
//     c    = value_b · s                 (block 0)
// ---------------------------------------------------------------------------
__global__ void k2(const float* __restrict__ vw, const float* __restrict__ vb) {
    const int tid = threadIdx.x;            // 512 threads
    const int j0 = blockIdx.x * 16;
    float acc = 0.0f;
#pragma unroll
    for (int j = 0; j < 16; j++)
        acc = fmaf(vw[(size_t)(j0 + j) * D + tid], g_s[j0 + j], acc);
    atomicAdd(&g_t[tid], acc);

    if (blockIdx.x == 0) {
        __shared__ float red[D];
        red[tid] = vb[tid] * g_s[tid];
        __syncthreads();
        for (int sft = 256; sft > 0; sft >>= 1) {
            if (tid < sft) red[tid] += red[tid + sft];
            __syncthreads();
        }
        if (tid == 0) g_c = red[0];
    }
}

// ---------------------------------------------------------------------------
// K3: pass 2: x[n] = inputs[n]·t + c, track global max (ordered-uint encode)
// ---------------------------------------------------------------------------
__global__ void __launch_bounds__(TPB, 4)
k3(const float* __restrict__ inp) {
    const int tid = threadIdx.x;
    const int lane = tid & 31;
    const int gw = (blockIdx.x * TPB + tid) >> 5;

    const float4* __restrict__ tp = (const float4*)g_t;
    const float4 w0 = tp[lane],      w1 = tp[lane + 32],
                 w2 = tp[lane + 64], w3 = tp[lane + 96];
    const float c = g_c;
    float maxv = -3.4e38f;

    for (int p = gw; p < NPAIRS; p += K3_WARPS) {
        const float4* __restrict__ rA = (const float4*)inp + (size_t)(2 * p) * (D / 4);
        const float4* __restrict__ rB = rA + (D / 4);
        const float4 a0 = rA[lane],      a1 = rA[lane + 32],
                     a2 = rA[lane + 64], a3 = rA[lane + 96];
        const float4 b0 = rB[lane],      b1 = rB[lane + 32],
                     b2 = rB[lane + 64], b3 = rB[lane + 96];

        float dA = (dot4(a0, w0) + dot4(a1, w1)) + (dot4(a2, w2) + dot4(a3, w3));
        float dB = (dot4(b0, w0) + dot4(b1, w1)) + (dot4(b2, w2) + dot4(b3, w3));
#pragma unroll
        for (int o = 16; o; o >>= 1) {
            dA += __shfl_xor_sync(FULL, dA, o);
            dB += __shfl_xor_sync(FULL, dB, o);
        }
        const float xA = dA + c;
        const float xB = dB + c;
        if (lane == 0) {
            g_x[2 * p]     = xA;
            g_x[2 * p + 1] = xB;
        }
        maxv = fmaxf(maxv, fmaxf(xA, xB));
    }

    if (lane == 0) {
        unsigned u = __float_as_uint(maxv);
        unsigned key = (u & 0x80000000u) ? ~u : (u | 0x80000000u);
        atomicMax(&g_maxkey, key);
    }
}

// ---------------------------------------------------------------------------
// K4: e = exp(x - max) (in place, float4), sumexp += block partial
// ---------------------------------------------------------------------------
__global__ void k4() {
    const unsigned key = g_maxkey;
    const unsigned ub = (key & 0x80000000u) ? (key & 0x7fffffffu) : ~key;
    const float gmax = __uint_as_float(ub);

    const int i = blockIdx.x * blockDim.x + threadIdx.x;   // 16384 threads
    float4* x4 = (float4*)g_x;
    float4 v = x4[i];
    v.x = expf(v.x - gmax); v.y = expf(v.y - gmax);
    v.z = expf(v.z - gmax); v.w = expf(v.w - gmax);
    x4[i] = v;

    float ws = warp_sum((v.x + v.y) + (v.z + v.w));
    __shared__ float sh[8];
    const int lane = threadIdx.x & 31, w = threadIdx.x >> 5;
    if (lane == 0) sh[w] = ws;
    __syncthreads();
    if (w == 0) {
        float s = (lane < 8) ? sh[lane] : 0.0f;
        s = warp_sum(s);
        if (lane == 0) atomicAdd(&g_sumexp, s);
    }
}

// ---------------------------------------------------------------------------
// K5: out = e / sumexp (float4)
// ---------------------------------------------------------------------------
__global__ void k5(float* __restrict__ out) {
    const int i = blockIdx.x * blockDim.x + threadIdx.x;   // 16384 threads
    const float inv = 1.0f / g_sumexp;
    const float4 v = ((const float4*)g_x)[i];
    float4 r;
    r.x = v.x * inv; r.y = v.y * inv; r.z = v.z * inv; r.w = v.w * inv;
    ((float4*)out)[i] = r;
}

// ---------------------------------------------------------------------------
extern "C" void kernel_launch(void* const* d_in, const int* in_sizes, int n_in,
                              void* d_out, int out_size) {
    (void)in_sizes; (void)n_in; (void)out_size;
    const float* inp = (const float*)d_in[0];   // [N, D]
    const float* kw  = (const float*)d_in[1];   // [1, D]
    const float* kb  = (const float*)d_in[2];   // [1]
    const float* vw  = (const float*)d_in[3];   // [D, D]
    const float* vb  = (const float*)d_in[4];   // [D]
    float* out = (float*)d_out;                 // [N, 1]

    k_init<<<1, D>>>();
    k1<<<K1_BLOCKS, TPB>>>(inp, kw, kb);
    k2<<<32, D>>>(vw, vb);
    k3<<<K3_BLOCKS, TPB>>>(inp);
    k4<<<N / 4 / 256, 256>>>();
    k5<<<N / 4 / 256, 256>>>(out);
}